// round 4
// baseline (speedup 1.0000x reference)
#include <cuda_runtime.h>
#include <cstdint>

// Tropical (max-times) matvec: out[b, i] = max_j M[i, j] * x[b, j]
// B = 256, n = 2048.
//
// Persistent kernel: 296 CTAs (2/SM on 148 SMs), 256 threads each.
// Work item = (output tile 128i x 64b) x (K-chunk of 64 j's).
//   64 tiles x 32 k-chunks = 2048 items, statically partitioned (6-7 per CTA).
// Per item: 4 double-buffered stages of BK=16 j's, register-prefetch pipeline
// that runs seamlessly across item boundaries.
// Thread tile TM=8 (i) x TN=4 (b); packed mul.rn.f32x2 + scalar FMNMX.
// Split-K partials in __device__ scratch, combined by a 32-way max kernel.

#define NN      2048
#define NB      256
#define BM      128
#define BN      64
#define BK      16
#define KC      64                   // K per item
#define SPI     (KC / BK)            // 4 stages per item
#define N_KC    (NN / KC)            // 32
#define N_TM    (NN / BM)            // 16
#define N_TB    (NB / BN)            // 4
#define N_TILES (N_TM * N_TB)        // 64
#define NITEMS  (N_TILES * N_KC)     // 2048
#define NCTAS   296
#define THREADS 256

// Split-K partials: [N_KC][NB][NN] = 64 MB
__device__ float g_part[(size_t)N_KC * NB * NN];

__device__ __forceinline__ unsigned long long dup_f32(float v) {
    unsigned long long r;
    unsigned int u = __float_as_uint(v);
    asm("mov.b64 %0, {%1, %1};" : "=l"(r) : "r"(u));
    return r;
}

__device__ __forceinline__ unsigned long long mul_f32x2(unsigned long long a,
                                                        unsigned long long b) {
    unsigned long long r;
    asm("mul.rn.f32x2 %0, %1, %2;" : "=l"(r) : "l"(a), "l"(b));
    return r;
}

__device__ __forceinline__ void unpack2(unsigned long long p, float& lo, float& hi) {
    unsigned int l, h;
    asm("mov.b64 {%0, %1}, %2;" : "=r"(l), "=r"(h) : "l"(p));
    lo = __uint_as_float(l);
    hi = __uint_as_float(h);
}

__global__ __launch_bounds__(THREADS, 2)
void trop_mm_kernel(const float* __restrict__ x, const float* __restrict__ M)
{
    __shared__ float Ms[2][BK][BM + 4];   // [buf][j][i], pitch 132 (16B aligned rows)
    __shared__ float Xs[2][BK][BN + 4];   // [buf][j][b], pitch 68

    const int tid = threadIdx.x;
    const int tx  = tid & 15;            // b-direction: 16 groups of TN=4
    const int ty  = tid >> 4;            // i-direction: 16 groups of TM=8

    // loader coordinates
    const int m_row = tid >> 2;          // 0..63 (rows m_row, m_row+64)
    const int m_j4  = (tid & 3) * 4;     // 0,4,8,12
    const int x_b   = tid >> 2;          // 0..63
    const int x_j4  = (tid & 3) * 4;

    // static item partition
    const int it_beg = (int)(((long)blockIdx.x * NITEMS) / NCTAS);
    const int it_end = (int)(((long)(blockIdx.x + 1) * NITEMS) / NCTAS);
    const int s_beg  = it_beg * SPI;
    const int s_end  = it_end * SPI;

    // stage -> global pointers
    auto m_ptr = [&](int s) -> const float* {
        const int it   = s >> 2;                 // SPI = 4
        const int kt   = s & 3;
        const int tile = it & (N_TILES - 1);
        const int i0   = (tile & (N_TM - 1)) * BM;
        const int k0   = (it >> 6) * KC + kt * BK;
        return M + (size_t)(i0 + m_row) * NN + k0 + m_j4;
    };
    auto x_ptr = [&](int s) -> const float* {
        const int it   = s >> 2;
        const int kt   = s & 3;
        const int tile = it & (N_TILES - 1);
        const int b0   = (tile >> 4) * BN;       // N_TM = 16
        const int k0   = (it >> 6) * KC + kt * BK;
        return x + (size_t)(b0 + x_b) * NN + k0 + x_j4;
    };

    float4 mr0, mr1, xr;

    // ---- prologue: stage s_beg ----
    {
        const float* Mg = m_ptr(s_beg);
        mr0 = *(const float4*)(Mg);
        mr1 = *(const float4*)(Mg + (size_t)64 * NN);
        xr  = *(const float4*)(x_ptr(s_beg));
        const int b0 = s_beg & 1;
        Ms[b0][m_j4 + 0][m_row]      = mr0.x;
        Ms[b0][m_j4 + 1][m_row]      = mr0.y;
        Ms[b0][m_j4 + 2][m_row]      = mr0.z;
        Ms[b0][m_j4 + 3][m_row]      = mr0.w;
        Ms[b0][m_j4 + 0][m_row + 64] = mr1.x;
        Ms[b0][m_j4 + 1][m_row + 64] = mr1.y;
        Ms[b0][m_j4 + 2][m_row + 64] = mr1.z;
        Ms[b0][m_j4 + 3][m_row + 64] = mr1.w;
        Xs[b0][x_j4 + 0][x_b] = xr.x;
        Xs[b0][x_j4 + 1][x_b] = xr.y;
        Xs[b0][x_j4 + 2][x_b] = xr.z;
        Xs[b0][x_j4 + 3][x_b] = xr.w;
    }
    __syncthreads();

    const float NEG_INF = __int_as_float(0xff800000);
    float acc[8][4];
    #pragma unroll
    for (int a = 0; a < 8; a++)
        #pragma unroll
        for (int c = 0; c < 4; c++)
            acc[a][c] = NEG_INF;

    for (int s = s_beg; s < s_end; s++) {
        const int buf = s & 1;

        // prefetch next stage (possibly next item's first stage)
        const bool have_next = (s + 1 < s_end);
        if (have_next) {
            const float* Mg = m_ptr(s + 1);
            mr0 = *(const float4*)(Mg);
            mr1 = *(const float4*)(Mg + (size_t)64 * NN);
            xr  = *(const float4*)(x_ptr(s + 1));
        }

        // compute current stage
        #pragma unroll
        for (int kk = 0; kk < BK; kk++) {
            const float* msrc = &Ms[buf][kk][ty * 8];
            ulonglong2 mA = *(const ulonglong2*)(msrc);       // (m0,m1),(m2,m3)
            ulonglong2 mB = *(const ulonglong2*)(msrc + 4);   // (m4,m5),(m6,m7)
            float4 xv = *(const float4*)&Xs[buf][kk][tx * 4];

            unsigned long long xx[4];
            xx[0] = dup_f32(xv.x);
            xx[1] = dup_f32(xv.y);
            xx[2] = dup_f32(xv.z);
            xx[3] = dup_f32(xv.w);
            unsigned long long mp[4] = {mA.x, mA.y, mB.x, mB.y};

            #pragma unroll
            for (int q = 0; q < 4; q++)
                #pragma unroll
                for (int c = 0; c < 4; c++) {
                    float lo, hi;
                    unpack2(mul_f32x2(mp[q], xx[c]), lo, hi);
                    acc[2 * q + 0][c] = fmaxf(acc[2 * q + 0][c], lo);
                    acc[2 * q + 1][c] = fmaxf(acc[2 * q + 1][c], hi);
                }
        }

        // stage next tile into the other buffer
        if (have_next) {
            const int nb = buf ^ 1;
            Ms[nb][m_j4 + 0][m_row]      = mr0.x;
            Ms[nb][m_j4 + 1][m_row]      = mr0.y;
            Ms[nb][m_j4 + 2][m_row]      = mr0.z;
            Ms[nb][m_j4 + 3][m_row]      = mr0.w;
            Ms[nb][m_j4 + 0][m_row + 64] = mr1.x;
            Ms[nb][m_j4 + 1][m_row + 64] = mr1.y;
            Ms[nb][m_j4 + 2][m_row + 64] = mr1.z;
            Ms[nb][m_j4 + 3][m_row + 64] = mr1.w;
            Xs[nb][x_j4 + 0][x_b] = xr.x;
            Xs[nb][x_j4 + 1][x_b] = xr.y;
            Xs[nb][x_j4 + 2][x_b] = xr.z;
            Xs[nb][x_j4 + 3][x_b] = xr.w;
        }

        // item boundary: flush partials, reset accumulators
        if ((s & 3) == 3) {
            const int it   = s >> 2;
            const int tile = it & (N_TILES - 1);
            const int kc   = it >> 6;
            const int i0   = (tile & (N_TM - 1)) * BM;
            const int b0   = (tile >> 4) * BN;
            float* outp = g_part + (size_t)kc * (NB * NN);
            #pragma unroll
            for (int c = 0; c < 4; c++) {
                const int b = b0 + tx * 4 + c;
                float* row = outp + (size_t)b * NN + i0 + ty * 8;
                *(float4*)(row)     = make_float4(acc[0][c], acc[1][c], acc[2][c], acc[3][c]);
                *(float4*)(row + 4) = make_float4(acc[4][c], acc[5][c], acc[6][c], acc[7][c]);
            }
            #pragma unroll
            for (int a = 0; a < 8; a++)
                #pragma unroll
                for (int c = 0; c < 4; c++)
                    acc[a][c] = NEG_INF;
        }

        __syncthreads();
    }
}

__global__ __launch_bounds__(256, 1)
void combine_kernel(float* __restrict__ out)
{
    const int idx = blockIdx.x * 256 + threadIdx.x;   // float4 index
    const float4* p = (const float4*)g_part;
    const int stride = NB * NN / 4;                    // float4's per kc slice
    float4 r = p[idx];
    #pragma unroll
    for (int kc = 1; kc < N_KC; kc++) {
        float4 v = p[idx + (size_t)kc * stride];
        r.x = fmaxf(r.x, v.x);
        r.y = fmaxf(r.y, v.y);
        r.z = fmaxf(r.z, v.z);
        r.w = fmaxf(r.w, v.w);
    }
    ((float4*)out)[idx] = r;
}

extern "C" void kernel_launch(void* const* d_in, const int* in_sizes, int n_in,
                              void* d_out, int out_size)
{
    // x: [256, 2048] (524288), M: [2048, 2048] (4194304) — detect order defensively
    const float* x;
    const float* M;
    if (in_sizes[0] == NB * NN) { x = (const float*)d_in[0]; M = (const float*)d_in[1]; }
    else                        { x = (const float*)d_in[1]; M = (const float*)d_in[0]; }

    trop_mm_kernel<<<NCTAS, THREADS>>>(x, M);

    const int n4 = NB * NN / 4;                        // 131072 float4
    combine_kernel<<<n4 / 256, 256>>>((float*)d_out);
}

// round 5
// speedup vs baseline: 1.0632x; 1.0632x over previous
#include <cuda_runtime.h>
#include <cstdint>

// Tropical (max-times) matvec: out[b, i] = max_j M[i, j] * x[b, j]
// B = 256, n = 2048.
//
// 3 launches: init (encode -inf into d_out), persistent compute (296 CTAs,
// stage-balanced, atomicMax flush with order-preserving uint encoding),
// decode (uint -> float in place).
//
// Compute: tile 128i x 64b, BK=32 double-buffered smem (48 KB exactly, XOR
// swizzle), thread tile TM=8 x TN=4, packed mul.rn.f32x2 + scalar FMNMX.

#define NN      2048
#define NB      256
#define BM      128
#define BN      64
#define BK      32
#define N_TM    (NN / BM)            // 16
#define N_TB    (NB / BN)            // 4
#define N_TILES (N_TM * N_TB)        // 64
#define SPT     (NN / BK)            // 64 stages per tile
#define NSTAGES (N_TILES * SPT)      // 4096
#define NCTAS   296
#define THREADS 256

// order-preserving float -> uint (monotone for all finite floats)
__device__ __forceinline__ unsigned enc_f(float f) {
    unsigned b = __float_as_uint(f);
    return b ^ ((unsigned)((int)b >> 31) | 0x80000000u);
}

__global__ __launch_bounds__(256, 1)
void init_kernel(unsigned* __restrict__ outw)
{
    const int i = blockIdx.x * 256 + threadIdx.x;
    // enc(-inf) = 0x007FFFFF
    ((uint4*)outw)[i] = make_uint4(0x007FFFFFu, 0x007FFFFFu, 0x007FFFFFu, 0x007FFFFFu);
}

__global__ __launch_bounds__(256, 1)
void decode_kernel(unsigned* __restrict__ outw)
{
    const int i = blockIdx.x * 256 + threadIdx.x;
    uint4 v = ((uint4*)outw)[i];
    v.x = (v.x & 0x80000000u) ? (v.x ^ 0x80000000u) : ~v.x;
    v.y = (v.y & 0x80000000u) ? (v.y ^ 0x80000000u) : ~v.y;
    v.z = (v.z & 0x80000000u) ? (v.z ^ 0x80000000u) : ~v.z;
    v.w = (v.w & 0x80000000u) ? (v.w ^ 0x80000000u) : ~v.w;
    ((uint4*)outw)[i] = v;
}

__device__ __forceinline__ unsigned long long dup_f32(float v) {
    unsigned long long r;
    unsigned int u = __float_as_uint(v);
    asm("mov.b64 %0, {%1, %1};" : "=l"(r) : "r"(u));
    return r;
}
__device__ __forceinline__ unsigned long long mul_f32x2(unsigned long long a,
                                                        unsigned long long b) {
    unsigned long long r;
    asm("mul.rn.f32x2 %0, %1, %2;" : "=l"(r) : "l"(a), "l"(b));
    return r;
}
__device__ __forceinline__ void unpack2(unsigned long long p, float& lo, float& hi) {
    unsigned int l, h;
    asm("mov.b64 {%0, %1}, %2;" : "=r"(l), "=r"(h) : "l"(p));
    lo = __uint_as_float(l);
    hi = __uint_as_float(h);
}

__global__ __launch_bounds__(THREADS, 2)
void trop_mm_kernel(const float* __restrict__ x, const float* __restrict__ M,
                    unsigned* __restrict__ outw)
{
    // 48 KB static shared, XOR-swizzled (i' = i ^ 4*(j&7)) instead of padding
    __shared__ float Ms[2][BK][BM];   // 32768 B
    __shared__ float Xs[2][BK][BN];   // 16384 B

    const int tid = threadIdx.x;
    const int tx  = tid & 15;            // b-direction: 16 groups of TN=4
    const int ty  = tid >> 4;            // i-direction: 16 groups of TM=8

    // loader coordinates (fully coalesced 128B lines)
    const int m_row = tid >> 3;          // 0..31 -> rows m_row + 32k, k=0..3
    const int m_j4  = (tid & 7) * 4;     // j: 0,4,...,28
    const int x_b   = tid >> 3;          // 0..31 -> b, b+32
    const int x_j4  = (tid & 7) * 4;

    // stage-balanced static partition over 4096 stages
    const int s_beg = (int)(((long)blockIdx.x * NSTAGES) / NCTAS);
    const int s_end = (int)(((long)(blockIdx.x + 1) * NSTAGES) / NCTAS);

    float4 mreg[4];
    float4 xreg[2];

    // stage -> global load
    auto load_stage = [&](int s) {
        const int tile = s >> 6;                  // SPT = 64
        const int kt   = s & 63;
        const int i0   = (tile & (N_TM - 1)) * BM;
        const int b0   = (tile >> 4) * BN;
        const float* Mg = M + (size_t)(i0 + m_row) * NN + kt * BK + m_j4;
        const float* Xg = x + (size_t)(b0 + x_b) * NN + kt * BK + x_j4;
        #pragma unroll
        for (int k = 0; k < 4; k++)
            mreg[k] = *(const float4*)(Mg + (size_t)(32 * k) * NN);
        #pragma unroll
        for (int k = 0; k < 2; k++)
            xreg[k] = *(const float4*)(Xg + (size_t)(32 * k) * NN);
    };

    auto store_stage = [&](int buf) {
        #pragma unroll
        for (int k = 0; k < 4; k++) {
            const float* mf = (const float*)&mreg[k];
            #pragma unroll
            for (int d = 0; d < 4; d++) {
                const int j  = m_j4 + d;
                const int ii = (m_row + 32 * k) ^ (4 * (j & 7));
                Ms[buf][j][ii] = mf[d];
            }
        }
        #pragma unroll
        for (int k = 0; k < 2; k++) {
            const float* xf = (const float*)&xreg[k];
            #pragma unroll
            for (int d = 0; d < 4; d++) {
                const int j  = x_j4 + d;
                const int bb = (x_b + 32 * k) ^ (4 * (j & 7));
                Xs[buf][j][bb] = xf[d];
            }
        }
    };

    // prologue: stage s_beg into buffer 0
    load_stage(s_beg);
    store_stage(0);
    __syncthreads();

    const float NEG_INF = __int_as_float(0xff800000);
    float acc[8][4];
    #pragma unroll
    for (int a = 0; a < 8; a++)
        #pragma unroll
        for (int c = 0; c < 4; c++)
            acc[a][c] = NEG_INF;

    int ls = 0;
    for (int s = s_beg; s < s_end; s++, ls++) {
        const int  buf       = ls & 1;
        const bool have_next = (s + 1 < s_end);

        if (have_next)
            load_stage(s + 1);

        // compute current stage
        #pragma unroll 8
        for (int kk = 0; kk < BK; kk++) {
            const int sw = 4 * (kk & 7);
            const float4 m0 = *(const float4*)&Ms[buf][kk][(ty * 8)     ^ sw];
            const float4 m1 = *(const float4*)&Ms[buf][kk][(ty * 8 + 4) ^ sw];
            const float4 xv = *(const float4*)&Xs[buf][kk][(tx * 4)     ^ sw];

            unsigned long long mp[4];
            mp[0] = *(const unsigned long long*)&m0.x;
            mp[1] = *(const unsigned long long*)&m0.z;
            mp[2] = *(const unsigned long long*)&m1.x;
            mp[3] = *(const unsigned long long*)&m1.z;

            unsigned long long xx[4];
            xx[0] = dup_f32(xv.x);
            xx[1] = dup_f32(xv.y);
            xx[2] = dup_f32(xv.z);
            xx[3] = dup_f32(xv.w);

            #pragma unroll
            for (int q = 0; q < 4; q++)
                #pragma unroll
                for (int c = 0; c < 4; c++) {
                    float lo, hi;
                    unpack2(mul_f32x2(mp[q], xx[c]), lo, hi);
                    acc[2 * q + 0][c] = fmaxf(acc[2 * q + 0][c], lo);
                    acc[2 * q + 1][c] = fmaxf(acc[2 * q + 1][c], hi);
                }
        }

        if (have_next)
            store_stage(buf ^ 1);

        // flush at tile boundary or end of range: atomic max into encoded out
        if (((s & 63) == 63) || !have_next) {
            const int tile = s >> 6;
            const int i0   = (tile & (N_TM - 1)) * BM;
            const int b0   = (tile >> 4) * BN;
            #pragma unroll
            for (int c = 0; c < 4; c++) {
                const int b = b0 + tx * 4 + c;
                unsigned* row = outw + (size_t)b * NN + i0 + ty * 8;
                #pragma unroll
                for (int a = 0; a < 8; a++)
                    atomicMax(row + a, enc_f(acc[a][c]));
            }
            #pragma unroll
            for (int a = 0; a < 8; a++)
                #pragma unroll
                for (int c = 0; c < 4; c++)
                    acc[a][c] = NEG_INF;
        }

        __syncthreads();
    }
}

extern "C" void kernel_launch(void* const* d_in, const int* in_sizes, int n_in,
                              void* d_out, int out_size)
{
    // x: [256, 2048] (524288), M: [2048, 2048] (4194304) — detect order defensively
    const float* x;
    const float* M;
    if (in_sizes[0] == NB * NN) { x = (const float*)d_in[0]; M = (const float*)d_in[1]; }
    else                        { x = (const float*)d_in[1]; M = (const float*)d_in[0]; }

    unsigned* outw = (unsigned*)d_out;
    const int n4 = NB * NN / 4;              // 131072 uint4 slots

    init_kernel<<<n4 / 256, 256>>>(outw);
    trop_mm_kernel<<<NCTAS, THREADS>>>(x, M, outw);
    decode_kernel<<<n4 / 256, 256>>>(outw);
}